// round 1
// baseline (speedup 1.0000x reference)
#include <cuda_runtime.h>
#include <cstdint>

#define K0   16
#define DIN  4096
#define DOUT 4096
#define NROWS 8192
#define TPB  256
#define CPT  4                   // columns per thread
#define CPB  (TPB * CPT)         // 1024 columns per block
#define RPB  32                  // rows per block

__device__ float g_c;

// ---- packed f32x2 helpers (Blackwell FFMA2 path, PTX-only) ----
__device__ __forceinline__ unsigned long long ffma2(unsigned long long a,
                                                    unsigned long long b,
                                                    unsigned long long c) {
    unsigned long long d;
    asm("fma.rn.f32x2 %0, %1, %2, %3;" : "=l"(d) : "l"(a), "l"(b), "l"(c));
    return d;
}

__device__ __forceinline__ unsigned long long pack2(float lo, float hi) {
    unsigned long long r;
    asm("mov.b64 %0, {%1, %2};" : "=l"(r) : "f"(lo), "f"(hi));
    return r;
}

__device__ __forceinline__ float hsum2(unsigned long long v) {
    float lo, hi;
    asm("mov.b64 {%0, %1}, %2;" : "=f"(lo), "=f"(hi) : "l"(v));
    return lo + hi;
}

// ---- kernel 1: c = dot(W[0,16:4096], x[0,16:4096]) ----
__global__ void calc_c_kernel(const float* __restrict__ x,
                              const float* __restrict__ W) {
    __shared__ double sred[TPB];
    int tid = threadIdx.x;
    double s = 0.0;
    for (int j = K0 + tid; j < DOUT; j += TPB)
        s += (double)W[j] * (double)x[j];
    sred[tid] = s;
    __syncthreads();
    for (int off = TPB / 2; off > 0; off >>= 1) {
        if (tid < off) sred[tid] += sred[tid + off];
        __syncthreads();
    }
    if (tid == 0) g_c = (float)sred[0];
}

// ---- kernel 2: out[r,o] = c + sum_{k<16} x[r,k]*W[o,k] ----
// passed = (tstat < TAU) is identically false (tstat >= 0 > TAU), so the
// reference's where/mask collapses to this rank-16 update + scalar.
__global__ __launch_bounds__(TPB) void et_main_kernel(
    const float* __restrict__ x, const float* __restrict__ W,
    float* __restrict__ out)
{
    __shared__ __align__(16) unsigned long long sx[RPB][K0 / 2];  // 32 rows x 64B
    __shared__ float s_c;

    const int tid = threadIdx.x;
    const int colBase = blockIdx.x * CPB;
    const int rowBase = blockIdx.y * RPB;

    // cooperative load of the 32 row-prefixes x[r, 0:16] (4x LDS.128 worth each)
    if (tid < RPB * 4) {
        int r = tid >> 2, h = tid & 3;
        const ulonglong2* src =
            reinterpret_cast<const ulonglong2*>(x + (size_t)(rowBase + r) * DIN) + h;
        reinterpret_cast<ulonglong2*>(sx[r])[h] = *src;
    }
    if (tid == 0) s_c = g_c;

    // this thread's 4 consecutive W column-prefixes, packed as f32x2 in regs
    unsigned long long w[CPT][8];
    const int o0 = colBase + tid * CPT;
#pragma unroll
    for (int c = 0; c < CPT; ++c) {
        const ulonglong2* wp =
            reinterpret_cast<const ulonglong2*>(W + (size_t)(o0 + c) * DIN);
#pragma unroll
        for (int h = 0; h < 4; ++h) {
            ulonglong2 v = wp[h];
            w[c][2 * h]     = v.x;
            w[c][2 * h + 1] = v.y;
        }
    }
    __syncthreads();

    const unsigned long long cinit = pack2(s_c, 0.0f);  // lane0 carries +c
    size_t outIdx = (size_t)rowBase * DOUT + o0;

#pragma unroll 2
    for (int r = 0; r < RPB; ++r) {
        unsigned long long a0 = cinit, a1 = cinit, a2 = cinit, a3 = cinit;
        const ulonglong2* xr = reinterpret_cast<const ulonglong2*>(sx[r]);
#pragma unroll
        for (int h = 0; h < 4; ++h) {
            ulonglong2 xv = xr[h];   // LDS.128 broadcast (conflict-free)
            a0 = ffma2(xv.x, w[0][2 * h], a0);
            a1 = ffma2(xv.x, w[1][2 * h], a1);
            a2 = ffma2(xv.x, w[2][2 * h], a2);
            a3 = ffma2(xv.x, w[3][2 * h], a3);
            a0 = ffma2(xv.y, w[0][2 * h + 1], a0);
            a1 = ffma2(xv.y, w[1][2 * h + 1], a1);
            a2 = ffma2(xv.y, w[2][2 * h + 1], a2);
            a3 = ffma2(xv.y, w[3][2 * h + 1], a3);
        }
        float4 o;
        o.x = hsum2(a0);
        o.y = hsum2(a1);
        o.z = hsum2(a2);
        o.w = hsum2(a3);
        *reinterpret_cast<float4*>(out + outIdx) = o;  // STG.128, warp = 512B contig
        outIdx += DOUT;
    }
}

extern "C" void kernel_launch(void* const* d_in, const int* in_sizes, int n_in,
                              void* d_out, int out_size) {
    const float* x = (const float*)d_in[0];   // (4,2048,4096) f32
    const float* W = (const float*)d_in[1];   // (4096,4096)  f32
    float* out = (float*)d_out;               // (4,2048,4096) f32

    calc_c_kernel<<<1, TPB>>>(x, W);

    dim3 grid(DOUT / CPB, NROWS / RPB);       // (4, 256) = 1024 blocks
    et_main_kernel<<<grid, TPB>>>(x, W, out);
}

// round 3
// speedup vs baseline: 1.3087x; 1.3087x over previous
#include <cuda_runtime.h>
#include <cstdint>

#define K0    16
#define DIN   4096
#define DOUT  4096
#define NROWS 8192
#define TPB   128
#define CPT   4                   // columns per thread
#define CPB   (TPB * CPT)         // 512 columns per block
#define RPB   32                  // rows per block

// ---- packed f32x2 helpers (Blackwell FFMA2 path, PTX-only) ----
__device__ __forceinline__ unsigned long long ffma2(unsigned long long a,
                                                    unsigned long long b,
                                                    unsigned long long c) {
    unsigned long long d;
    asm("fma.rn.f32x2 %0, %1, %2, %3;" : "=l"(d) : "l"(a), "l"(b), "l"(c));
    return d;
}

__device__ __forceinline__ unsigned long long pack2(float lo, float hi) {
    unsigned long long r;
    asm("mov.b64 %0, {%1, %2};" : "=l"(r) : "f"(lo), "f"(hi));
    return r;
}

__device__ __forceinline__ float hsum2(unsigned long long v) {
    float lo, hi;
    asm("mov.b64 {%0, %1}, %2;" : "=f"(lo), "=f"(hi) : "l"(v));
    return lo + hi;
}

// out[r,o] = c + sum_{k<16} x[r,k]*W[o,k]
// (tstat >= 0 > TAU, so the reference's mask is identically "active";
//  the whole op collapses to a rank-16 update plus the scalar c.)
// c = dot(W[0,16:4096], x[0,16:4096]) is computed redundantly per block:
// the 32KB it reads is L2-resident after the first wave, which is far
// cheaper than a serial single-block kernel + extra graph node.
__global__ __launch_bounds__(TPB) void et_fused_kernel(
    const float* __restrict__ x, const float* __restrict__ W,
    float* __restrict__ out)
{
    __shared__ __align__(16) unsigned long long sx[RPB][K0 / 2];  // 32 rows x 64B
    __shared__ float sred[TPB / 32];
    __shared__ float s_c;

    const int tid  = threadIdx.x;
    const int lane = tid & 31;
    const int warp = tid >> 5;
    const int colBase = blockIdx.x * CPB;
    const int rowBase = blockIdx.y * RPB;

    // ---- prologue A: cooperative load of 32 row-prefixes x[r, 0:16] ----
    {
        int r = tid >> 2, h = tid & 3;   // exactly 128 threads = 32 rows x 4 chunks
        const ulonglong2* src =
            reinterpret_cast<const ulonglong2*>(x + (size_t)(rowBase + r) * DIN) + h;
        reinterpret_cast<ulonglong2*>(sx[r])[h] = *src;
    }

    // ---- prologue B: c = dot(W[0,16:], x[0,16:]) as vectorized f32 reduce ----
    {
        const float4* x4 = reinterpret_cast<const float4*>(x);
        const float4* w4 = reinterpret_cast<const float4*>(W);
        float acc = 0.0f;
#pragma unroll
        for (int k = 0; k < 8; ++k) {
            int fidx = 4 + tid + k * TPB;          // float4 index, covers [4,1024)
            if (fidx < DIN / 4) {
                float4 xv = x4[fidx];
                float4 wv = w4[fidx];
                acc += xv.x * wv.x + xv.y * wv.y + xv.z * wv.z + xv.w * wv.w;
            }
        }
#pragma unroll
        for (int off = 16; off > 0; off >>= 1)
            acc += __shfl_xor_sync(0xFFFFFFFFu, acc, off);
        if (lane == 0) sred[warp] = acc;
    }

    // ---- prologue C: this thread's 4 W column-prefixes into registers ----
    unsigned long long w[CPT][8];
    const int o0 = colBase + tid * CPT;
#pragma unroll
    for (int c = 0; c < CPT; ++c) {
        const ulonglong2* wp =
            reinterpret_cast<const ulonglong2*>(W + (size_t)(o0 + c) * DIN);
#pragma unroll
        for (int h = 0; h < 4; ++h) {
            ulonglong2 v = wp[h];
            w[c][2 * h]     = v.x;
            w[c][2 * h + 1] = v.y;
        }
    }
    __syncthreads();

    if (tid == 0) {
        float c = 0.0f;
#pragma unroll
        for (int i = 0; i < TPB / 32; ++i) c += sred[i];
        s_c = c;
    }
    __syncthreads();

    // ---- main loop ----
    const unsigned long long cinit = pack2(s_c, 0.0f);  // lane0 carries +c
    size_t outIdx = (size_t)rowBase * DOUT + o0;

#pragma unroll 4
    for (int r = 0; r < RPB; ++r) {
        unsigned long long a0 = cinit, a1 = cinit, a2 = cinit, a3 = cinit;
        const ulonglong2* xr = reinterpret_cast<const ulonglong2*>(sx[r]);
#pragma unroll
        for (int h = 0; h < 4; ++h) {
            ulonglong2 xv = xr[h];   // LDS.128 broadcast (conflict-free)
            a0 = ffma2(xv.x, w[0][2 * h], a0);
            a1 = ffma2(xv.x, w[1][2 * h], a1);
            a2 = ffma2(xv.x, w[2][2 * h], a2);
            a3 = ffma2(xv.x, w[3][2 * h], a3);
            a0 = ffma2(xv.y, w[0][2 * h + 1], a0);
            a1 = ffma2(xv.y, w[1][2 * h + 1], a1);
            a2 = ffma2(xv.y, w[2][2 * h + 1], a2);
            a3 = ffma2(xv.y, w[3][2 * h + 1], a3);
        }
        float4 o;
        o.x = hsum2(a0);
        o.y = hsum2(a1);
        o.z = hsum2(a2);
        o.w = hsum2(a3);
        *reinterpret_cast<float4*>(out + outIdx) = o;  // STG.128, warp = 512B contig
        outIdx += DOUT;
    }
}

extern "C" void kernel_launch(void* const* d_in, const int* in_sizes, int n_in,
                              void* d_out, int out_size) {
    const float* x = (const float*)d_in[0];   // (4,2048,4096) f32
    const float* W = (const float*)d_in[1];   // (4096,4096)  f32
    float* out = (float*)d_out;               // (4,2048,4096) f32

    dim3 grid(DOUT / CPB, NROWS / RPB);       // (8, 256) = 2048 blocks
    et_fused_kernel<<<grid, TPB>>>(x, W, out);
}

// round 4
// speedup vs baseline: 1.4289x; 1.0919x over previous
#include <cuda_runtime.h>
#include <cstdint>

#define K0     16
#define DIN    4096
#define DOUT   4096
#define NROWS  8192
#define TPB    128
#define CPT    4                    // columns per thread
#define CPB    (TPB * CPT)          // 512 columns per block
#define RPB    32                   // rows per tile
#define NTILES (NROWS / RPB)        // 256
#define YBLKS  86                   // persistent row-groups: 84 blocks do 3 tiles

// ---- packed f32x2 helpers (Blackwell FFMA2 path, PTX-only) ----
__device__ __forceinline__ unsigned long long ffma2(unsigned long long a,
                                                    unsigned long long b,
                                                    unsigned long long c) {
    unsigned long long d;
    asm("fma.rn.f32x2 %0, %1, %2, %3;" : "=l"(d) : "l"(a), "l"(b), "l"(c));
    return d;
}

__device__ __forceinline__ unsigned long long pack2(float lo, float hi) {
    unsigned long long r;
    asm("mov.b64 %0, {%1, %2};" : "=l"(r) : "f"(lo), "f"(hi));
    return r;
}

__device__ __forceinline__ float hsum2(unsigned long long v) {
    float lo, hi;
    asm("mov.b64 {%0, %1}, %2;" : "=f"(lo), "=f"(hi) : "l"(v));
    return lo + hi;
}

// out[r,o] = c + sum_{k<16} x[r,k]*W[o,k]
// (tstat >= 0 > TAU, so the reference's mask is identically "active";
//  the op collapses to a rank-16 update plus the scalar c.)
// Persistent blocks: each block owns 512 columns, computes c + loads W once,
// then loops over ~3 row-tiles with double-buffered x prefetch.
__global__ __launch_bounds__(TPB, 5) void et_persistent_kernel(
    const float* __restrict__ x, const float* __restrict__ W,
    float* __restrict__ out)
{
    __shared__ __align__(16) unsigned long long sx[2][RPB][K0 / 2]; // 2 x 2KB
    __shared__ float sred[TPB / 32];
    __shared__ float s_c;

    const int tid  = threadIdx.x;
    const int lane = tid & 31;
    const int warp = tid >> 5;
    const int o0   = blockIdx.x * CPB + tid * CPT;

    const int r = tid >> 2, h = tid & 3;   // this thread's x-chunk: row r, 16B chunk h

    int t = blockIdx.y;                    // first tile

    // ---- prologue: issue tile-0 x prefetch early ----
    ulonglong2 pf = *(reinterpret_cast<const ulonglong2*>(
                          x + (size_t)(t * RPB + r) * DIN) + h);

    // ---- c = dot(W[0,16:], x[0,16:]) (f32 vectorized + warp reduce) ----
    {
        const float4* x4 = reinterpret_cast<const float4*>(x);
        const float4* w4 = reinterpret_cast<const float4*>(W);
        float acc = 0.0f;
#pragma unroll
        for (int k = 0; k < 8; ++k) {
            int fidx = 4 + tid + k * TPB;          // float4 index, [4,1024)
            if (fidx < DIN / 4) {
                float4 xv = x4[fidx];
                float4 wv = w4[fidx];
                acc += xv.x * wv.x + xv.y * wv.y + xv.z * wv.z + xv.w * wv.w;
            }
        }
#pragma unroll
        for (int off = 16; off > 0; off >>= 1)
            acc += __shfl_xor_sync(0xFFFFFFFFu, acc, off);
        if (lane == 0) sred[warp] = acc;
    }

    // ---- W column-prefixes into registers (lives for the whole kernel) ----
    unsigned long long w[CPT][8];
#pragma unroll
    for (int c = 0; c < CPT; ++c) {
        const ulonglong2* wp =
            reinterpret_cast<const ulonglong2*>(W + (size_t)(o0 + c) * DIN);
#pragma unroll
        for (int hh = 0; hh < 4; ++hh) {
            ulonglong2 v = wp[hh];
            w[c][2 * hh]     = v.x;
            w[c][2 * hh + 1] = v.y;
        }
    }

    // commit tile-0 x to smem buffer 0 + finish c reduction
    reinterpret_cast<ulonglong2*>(sx[0][r])[h] = pf;
    __syncthreads();
    if (tid == 0) {
        float c = 0.0f;
#pragma unroll
        for (int i = 0; i < TPB / 32; ++i) c += sred[i];
        s_c = c;
    }
    __syncthreads();

    const unsigned long long cinit = pack2(s_c, 0.0f);  // lane0 carries +c
    int buf = 0;

    // ---- persistent tile loop ----
    for (;;) {
        const int tn = t + YBLKS;
        const bool more = tn < NTILES;

        // prefetch next tile's x chunk into registers (covered by compute)
        ulonglong2 pf2;
        if (more)
            pf2 = *(reinterpret_cast<const ulonglong2*>(
                        x + (size_t)(tn * RPB + r) * DIN) + h);

        size_t outIdx = (size_t)t * RPB * DOUT + o0;
#pragma unroll 4
        for (int rr = 0; rr < RPB; ++rr) {
            unsigned long long a0 = cinit, a1 = cinit, a2 = cinit, a3 = cinit;
            const ulonglong2* xr = reinterpret_cast<const ulonglong2*>(sx[buf][rr]);
#pragma unroll
            for (int hh = 0; hh < 4; ++hh) {
                ulonglong2 xv = xr[hh];   // LDS.128 broadcast (conflict-free)
                a0 = ffma2(xv.x, w[0][2 * hh], a0);
                a1 = ffma2(xv.x, w[1][2 * hh], a1);
                a2 = ffma2(xv.x, w[2][2 * hh], a2);
                a3 = ffma2(xv.x, w[3][2 * hh], a3);
                a0 = ffma2(xv.y, w[0][2 * hh + 1], a0);
                a1 = ffma2(xv.y, w[1][2 * hh + 1], a1);
                a2 = ffma2(xv.y, w[2][2 * hh + 1], a2);
                a3 = ffma2(xv.y, w[3][2 * hh + 1], a3);
            }
            float4 o;
            o.x = hsum2(a0);
            o.y = hsum2(a1);
            o.z = hsum2(a2);
            o.w = hsum2(a3);
            *reinterpret_cast<float4*>(out + outIdx) = o;  // STG.128
            outIdx += DOUT;
        }

        if (!more) break;

        // write next tile into the other buffer (no one reads it yet -> no
        // pre-barrier needed), then one barrier before consuming it
        reinterpret_cast<ulonglong2*>(sx[buf ^ 1][r])[h] = pf2;
        __syncthreads();
        buf ^= 1;
        t = tn;
    }
}

extern "C" void kernel_launch(void* const* d_in, const int* in_sizes, int n_in,
                              void* d_out, int out_size) {
    const float* x = (const float*)d_in[0];   // (4,2048,4096) f32
    const float* W = (const float*)d_in[1];   // (4096,4096)  f32
    float* out = (float*)d_out;               // (4,2048,4096) f32

    dim3 grid(DOUT / CPB, YBLKS);             // (8, 86) = 688 persistent blocks
    et_persistent_kernel<<<grid, TPB>>>(x, W, out);
}